// round 15
// baseline (speedup 1.0000x reference)
#include <cuda_runtime.h>
#include <cuda_bf16.h>
#include <cstdint>

// Problem constants (fixed by dataset: N1=N2=50000, F=1024, D=128, H1=64, H2=32, E=1e6)
#define FDIM  1024
#define DDIM  128
#define H1DIM 64
#define H2DIM 32
#define NMAX  50000

// ---------------------------------------------------------------------------
// Scratch (static device globals — no runtime allocation allowed)
// ---------------------------------------------------------------------------
__device__ __nv_bfloat16 g_WcTh[2 * H1DIM * FDIM];  // folded W, transposed [half][n][k], hi split
__device__ __nv_bfloat16 g_WcTl[2 * H1DIM * FDIM];  // lo split
__device__ __align__(16) unsigned char g_Wm2F[8192]; // Wm2 frag table (edge layer-2)
__device__ float g_bc1[H1DIM];
__device__ float g_bc2[H1DIM];
__device__ float g_g1[NMAX * H1DIM];    // x_gene @ Wc1 + bc1   [50000,64]
__device__ float g_g2[NMAX * H1DIM];    // x_cell @ Wc2 + bc2   [50000,64]

__device__ __forceinline__ uint32_t smem_u32(const void* p) {
    uint32_t a;
    asm("{ .reg .u64 t; cvta.to.shared.u64 t, %1; cvt.u32.u64 %0, t; }" : "=r"(a) : "l"(p));
    return a;
}

#define LDSM_X4(r, a) \
    asm volatile("ldmatrix.sync.aligned.m8n8.x4.shared.b16 {%0,%1,%2,%3}, [%4];" \
                 : "=r"((r)[0]), "=r"((r)[1]), "=r"((r)[2]), "=r"((r)[3]) : "r"(a))

#define MMA_BF16(c, a, b0, b1) \
    asm volatile("mma.sync.aligned.m16n8k16.row.col.f32.bf16.bf16.f32 " \
                 "{%0,%1,%2,%3}, {%4,%5,%6,%7}, {%8,%9}, {%0,%1,%2,%3};" \
                 : "+f"((c)[0]), "+f"((c)[1]), "+f"((c)[2]), "+f"((c)[3]) \
                 : "r"((a)[0]), "r"((a)[1]), "r"((a)[2]), "r"((a)[3]), "r"(b0), "r"(b1))

#define CP_ASYNC16(dst, src) \
    asm volatile("cp.async.ca.shared.global [%0], [%1], 16;" :: "r"(dst), "l"(src))
#define CP_COMMIT() asm volatile("cp.async.commit_group;" ::: "memory")
#define CP_WAIT1()  asm volatile("cp.async.wait_group 1;" ::: "memory")

__device__ __forceinline__ void split_bf16x2(float a, float b, uint32_t& hi, uint32_t& lo) {
    __nv_bfloat16 ha = __float2bfloat16(a);
    __nv_bfloat16 hb = __float2bfloat16(b);
    __nv_bfloat162 h = __halves2bfloat162(ha, hb);
    __nv_bfloat162 l = __floats2bfloat162_rn(a - __bfloat162float(ha),
                                             b - __bfloat162float(hb));
    hi = *(uint32_t*)&h;
    lo = *(uint32_t*)&l;
}

// ---------------------------------------------------------------------------
// Kernel 1: ALL folds in one launch (R12 config + coalesced output staging).
// grid (129, 2), 256 threads.
//   bx < 128         : weight fold, 8 f-rows x 64 j-cols; outputs staged in
//                      smem and written as one 16B uint4 per (j, split)
//   bx == 128, by==0 : bias fold
//   bx == 128, by==1 : Wm2 -> mma-fragment table
// Arithmetic per output identical to R12 (serial fmaf over ascending d).
// ---------------------------------------------------------------------------
#define BLKF 8

__global__ void __launch_bounds__(256)
fold_all_kernel(const float* __restrict__ W1,
                const float* __restrict__ W2,
                const float* __restrict__ Wm1,
                const float* __restrict__ b1,
                const float* __restrict__ b2,
                const float* __restrict__ bm1,
                const float* __restrict__ Wm2) {
    __shared__ float Wm1T[H1DIM][DDIM + 4];   // transposed: [j][d], 33.8KB
    __shared__ float Ws[BLKF][DDIM];          // 4KB
    __shared__ __align__(16) __nv_bfloat16 WcHs[H1DIM][BLKF];  // 1KB out staging (hi)
    __shared__ __align__(16) __nv_bfloat16 WcLs[H1DIM][BLKF];  // 1KB out staging (lo)

    const int t    = threadIdx.x;
    const int half = blockIdx.y;

    if (blockIdx.x < 128) {
        const int f0   = blockIdx.x * BLKF;
        const float* W = half ? W2 : W1;
        const int off  = half * DDIM;

        // Load Wm1 half transposed: Wm1T[j][d] = Wm1[(off+d)*64 + j]
        for (int i = t; i < DDIM * H1DIM; i += 256) {
            const int d = i >> 6;
            const int j = i & 63;
            Wm1T[j][d] = Wm1[(off + d) * H1DIM + j];
        }
        // Load W tile [8][128] coalesced
        for (int i = t; i < BLKF * DDIM; i += 256)
            Ws[i >> 7][i & 127] = W[(size_t)(f0 + (i >> 7)) * DDIM + (i & 127)];
        __syncthreads();

        const int j  = t & 63;
        const int fi = t >> 6;            // 0..3
#pragma unroll
        for (int r = 0; r < 2; r++) {
            const int fr = fi + 4 * r;    // 0..7
            float acc = 0.f;
#pragma unroll
            for (int d4 = 0; d4 < DDIM / 4; d4++) {
                const float4 wv = *(const float4*)&Ws[fr][d4 * 4];      // warp broadcast
                const float4 mv = *(const float4*)&Wm1T[j][d4 * 4];     // vector LDS
                acc = fmaf(wv.x, mv.x, acc);
                acc = fmaf(wv.y, mv.y, acc);
                acc = fmaf(wv.z, mv.z, acc);
                acc = fmaf(wv.w, mv.w, acc);
            }
            __nv_bfloat16 hi = __float2bfloat16(acc);
            __nv_bfloat16 lo = __float2bfloat16(acc - __bfloat162float(hi));
            WcHs[j][fr] = hi;            // stage in smem (tiny)
            WcLs[j][fr] = lo;
        }
        __syncthreads();

        // Coalesced writeback: thread j emits one 16B uint4 per split
        // (8 contiguous bf16 along k at row n = half*64+j, cols f0..f0+7).
        if (t < H1DIM) {
            const size_t rowoff = (size_t)(half * H1DIM + t) * FDIM + f0;
            *(uint4*)&g_WcTh[rowoff] = *(const uint4*)&WcHs[t][0];
            *(uint4*)&g_WcTl[rowoff] = *(const uint4*)&WcLs[t][0];
        }
    } else if (half == 0) {
        // Bias fold (threads 0..127)
        if (t >= 128) return;
        const int j = t & 63;
        const int h2 = t >> 6;
        const float* b = h2 ? b2 : b1;
        const int off = h2 * DDIM;
        float acc = h2 ? 0.f : bm1[j];
#pragma unroll 8
        for (int d = 0; d < DDIM; d++)
            acc = fmaf(b[d], Wm1[(off + d) * H1DIM + j], acc);
        (h2 ? g_bc2 : g_bc1)[j] = acc;
    } else {
        // Wm2 [64,32] -> bf16 hi/lo frag table (validated mapping)
        for (int idx = t; idx < H2DIM * H1DIM; idx += 256) {
            const int n = idx & (H2DIM - 1);
            const int k = idx >> 5;
            float v = Wm2[k * H2DIM + n];
            __nv_bfloat16 hi = __float2bfloat16(v);
            __nv_bfloat16 lo = __float2bfloat16(v - __bfloat162float(hi));
            const int ks = k >> 4, G = n >> 4, rr = n & 7, mh = (n >> 3) & 1, kb = k & 15;
            const int lane = rr * 4 + ((kb & 7) >> 1);
            const int reg  = mh * 2 + (kb >> 3);
            const int base = ((ks * 2 + G) * 2) * 512 + lane * 16 + reg * 4 + (kb & 1) * 2;
            *(__nv_bfloat16*)(g_Wm2F + base)       = hi;
            *(__nv_bfloat16*)(g_Wm2F + base + 512) = lo;
        }
    }
}

// ---------------------------------------------------------------------------
// Kernel 2: mma.sync bf16-split projection GEMM — UNCHANGED (proven 129.3-129.6us).
// ---------------------------------------------------------------------------
#define A_STRIDE   80
#define A_ST_BYTES (128 * A_STRIDE)
#define B_STRIDE   80
#define B_ST_BYTES (H1DIM * B_STRIDE)
#define OFF_A_HI   0
#define OFF_A_LO   (2 * A_ST_BYTES)
#define OFF_B_HI   (4 * A_ST_BYTES)
#define OFF_B_LO   (OFF_B_HI + 3 * B_ST_BYTES)
#define SM_TOTAL   (OFF_B_LO + 3 * B_ST_BYTES)

__global__ void __launch_bounds__(256)
proj_mma_kernel(const float* __restrict__ x_gene,
                const float* __restrict__ x_cell,
                int N1, int N2) {
    extern __shared__ __align__(16) char smem[];

    const int t   = threadIdx.x;
    const int wid = t >> 5;
    const int l   = t & 31;
    const int half = blockIdx.y;

    const float* x = half ? x_cell : x_gene;
    const char* WTh = (const char*)(g_WcTh + half * H1DIM * FDIM);
    const char* WTl = (const char*)(g_WcTl + half * H1DIM * FDIM);
    const float* bc = half ? g_bc2 : g_bc1;
    float* g = half ? g_g2 : g_g1;
    const int M  = half ? N2 : N1;
    const int m0 = blockIdx.x * 128;
    if (m0 >= M) return;

    const uint32_t sb = smem_u32(smem);

    const int m0w = (wid & 3) * 32;
    const int n0w = (wid >> 2) * 32;

    float acc[2][4][4] = {};

    const float4* xv = (const float4*)x;
    const int arow = t >> 3;
    const int ac4  = t & 7;
    const int brow = t >> 2;
    const int bq   = t & 3;

    size_t gmr[4];
#pragma unroll
    for (int r = 0; r < 4; r++) {
        int gm = m0 + arow + 32 * r;
        gmr[r] = (size_t)((gm < M) ? gm : (M - 1));
    }

    uint32_t a_off[2], b_off[2];
#pragma unroll
    for (int mt = 0; mt < 2; mt++)
        a_off[mt] = (uint32_t)((m0w + mt * 16 + (l & 15)) * A_STRIDE + (l >> 4) * 16);
#pragma unroll
    for (int gp = 0; gp < 2; gp++)
        b_off[gp] = (uint32_t)((n0w + gp * 16 + ((l >> 4) * 8) + (l & 7)) * B_STRIDE
                               + ((l >> 3) & 1) * 16);

    const size_t bgo = (size_t)brow * (FDIM * 2) + bq * 16;
    const uint32_t bso = (uint32_t)(brow * B_STRIDE + bq * 16);
    const uint32_t a_sts = (uint32_t)(arow * A_STRIDE + ac4 * 8);

    float4 va[4];
#pragma unroll
    for (int r = 0; r < 4; r++) va[r] = xv[gmr[r] * (FDIM / 4) + ac4];
    CP_ASYNC16(sb + OFF_B_HI + bso, WTh + bgo);
    CP_ASYNC16(sb + OFF_B_LO + bso, WTl + bgo);
    CP_COMMIT();
    CP_ASYNC16(sb + OFF_B_HI + B_ST_BYTES + bso, WTh + bgo + 64);
    CP_ASYNC16(sb + OFF_B_LO + B_ST_BYTES + bso, WTl + bgo + 64);
    CP_COMMIT();
#pragma unroll
    for (int r = 0; r < 4; r++) {
        uint2 uh, ul;
        split_bf16x2(va[r].x, va[r].y, uh.x, ul.x);
        split_bf16x2(va[r].z, va[r].w, uh.y, ul.y);
        *(uint2*)(smem + OFF_A_HI + a_sts + 32 * r * A_STRIDE) = uh;
        *(uint2*)(smem + OFF_A_LO + a_sts + 32 * r * A_STRIDE) = ul;
    }
#pragma unroll
    for (int r = 0; r < 4; r++) va[r] = xv[gmr[r] * (FDIM / 4) + 8 + ac4];
    CP_WAIT1();
    __syncthreads();

    int b_cur = 0;
    for (int kk = 0; kk < FDIM / 32; kk++) {
        const int a_cur = kk & 1;
        if (kk < FDIM / 32 - 1) {
            const uint32_t abase = (uint32_t)((a_cur ^ 1) * A_ST_BYTES);
#pragma unroll
            for (int r = 0; r < 4; r++) {
                uint2 uh, ul;
                split_bf16x2(va[r].x, va[r].y, uh.x, ul.x);
                split_bf16x2(va[r].z, va[r].w, uh.y, ul.y);
                *(uint2*)(smem + OFF_A_HI + abase + a_sts + 32 * r * A_STRIDE) = uh;
                *(uint2*)(smem + OFF_A_LO + abase + a_sts + 32 * r * A_STRIDE) = ul;
            }
        }
        if (kk < FDIM / 32 - 2) {
#pragma unroll
            for (int r = 0; r < 4; r++)
                va[r] = xv[gmr[r] * (FDIM / 4) + (kk + 2) * 8 + ac4];
        }
        if (kk < FDIM / 32 - 2) {
            int b2 = b_cur + 2; if (b2 >= 3) b2 -= 3;
            const uint32_t nb = (uint32_t)(b2 * B_ST_BYTES);
            CP_ASYNC16(sb + OFF_B_HI + nb + bso, WTh + bgo + (size_t)(kk + 2) * 64);
            CP_ASYNC16(sb + OFF_B_LO + nb + bso, WTl + bgo + (size_t)(kk + 2) * 64);
        }
        CP_COMMIT();

        const uint32_t ah_base = sb + OFF_A_HI + a_cur * A_ST_BYTES;
        const uint32_t al_base = sb + OFF_A_LO + a_cur * A_ST_BYTES;
        const uint32_t bh_base = sb + OFF_B_HI + b_cur * B_ST_BYTES;
        const uint32_t bl_base = sb + OFF_B_LO + b_cur * B_ST_BYTES;
#pragma unroll
        for (int kc = 0; kc < 2; kc++) {
            const uint32_t ko = kc * 32;
            uint32_t ah[2][4], al[2][4], bh[2][4], bl[2][4];
#pragma unroll
            for (int mt = 0; mt < 2; mt++) {
                LDSM_X4(ah[mt], ah_base + a_off[mt] + ko);
                LDSM_X4(al[mt], al_base + a_off[mt] + ko);
            }
#pragma unroll
            for (int gp = 0; gp < 2; gp++) {
                LDSM_X4(bh[gp], bh_base + b_off[gp] + ko);
                LDSM_X4(bl[gp], bl_base + b_off[gp] + ko);
            }
#pragma unroll
            for (int mt = 0; mt < 2; mt++) {
#pragma unroll
                for (int nt = 0; nt < 4; nt++) {
                    const int gp = nt >> 1;
                    const int br = (nt & 1) * 2;
                    MMA_BF16(acc[mt][nt], ah[mt], bh[gp][br], bh[gp][br + 1]);
                    MMA_BF16(acc[mt][nt], ah[mt], bl[gp][br], bl[gp][br + 1]);
                    MMA_BF16(acc[mt][nt], al[mt], bh[gp][br], bh[gp][br + 1]);
                }
            }
        }
        CP_WAIT1();
        __syncthreads();
        b_cur = (b_cur == 2) ? 0 : b_cur + 1;
    }

#pragma unroll
    for (int mt = 0; mt < 2; mt++) {
#pragma unroll
        for (int nt = 0; nt < 4; nt++) {
            const int col = n0w + nt * 8 + 2 * (l & 3);
            const float bx = bc[col], by = bc[col + 1];
            const int r0 = m0 + m0w + mt * 16 + (l >> 2);
            if (r0 < M) {
                float2 o; o.x = acc[mt][nt][0] + bx; o.y = acc[mt][nt][1] + by;
                *(float2*)&g[(size_t)r0 * H1DIM + col] = o;
            }
            const int r1 = r0 + 8;
            if (r1 < M) {
                float2 o; o.x = acc[mt][nt][2] + bx; o.y = acc[mt][nt][3] + by;
                *(float2*)&g[(size_t)r1 * H1DIM + col] = o;
            }
        }
    }
}

// ---------------------------------------------------------------------------
// Kernel 3: barrier-free edge stage — UNCHANGED (proven, measured 58.9us).
// ---------------------------------------------------------------------------
#define EV_STRIDE 144

__global__ void __launch_bounds__(128)
edge_kernel(const int* __restrict__ eidx,
            const float* __restrict__ bm2,
            const float* __restrict__ Wm3,
            const float* __restrict__ bm3,
            float* __restrict__ out,
            int E, int N1, int N2) {
    __shared__ __align__(16) char vhi[128 * EV_STRIDE];
    __shared__ __align__(16) char vlo[128 * EV_STRIDE];

    const int t  = threadIdx.x;
    const int w  = t >> 5;
    const int l  = t & 31;
    const int e0 = blockIdx.x * 128;

    int s_l, d_l;
    {
        int eg = e0 + w * 32 + l;
        int ec = (eg < E) ? eg : (E - 1);
        int s = eidx[ec];
        int d = eidx[E + ec];
        s_l = (s < 0) ? 0 : (s >= N1 ? N1 - 1 : s);
        d_l = (d < 0) ? 0 : (d >= N2 ? N2 - 1 : d);
    }

    const float4* g1v = (const float4*)g_g1;
    const float4* g2v = (const float4*)g_g2;
    const int c = l & 15;
#pragma unroll
    for (int it = 0; it < 16; it++) {
        const int e = (l >> 4) + 2 * it;
        const int si = __shfl_sync(0xffffffffu, s_l, e);
        const int di = __shfl_sync(0xffffffffu, d_l, e);
        float4 a = g1v[si * 16 + c];
        float4 b = g2v[di * 16 + c];
        float v0 = fmaxf(a.x + b.x, 0.f);
        float v1 = fmaxf(a.y + b.y, 0.f);
        float v2 = fmaxf(a.z + b.z, 0.f);
        float v3 = fmaxf(a.w + b.w, 0.f);
        uint2 uh, ul;
        split_bf16x2(v0, v1, uh.x, ul.x);
        split_bf16x2(v2, v3, uh.y, ul.y);
        const uint32_t off = (uint32_t)((w * 32 + e) * EV_STRIDE + c * 8);
        *(uint2*)(vhi + off) = uh;
        *(uint2*)(vlo + off) = ul;
    }
    __syncwarp();

    const uint32_t vb_hi = smem_u32(vhi);
    const uint32_t vb_lo = smem_u32(vlo);
    uint32_t a_hi[2], a_lo[2];
#pragma unroll
    for (int mt = 0; mt < 2; mt++) {
        const uint32_t off = (uint32_t)((w * 32 + mt * 16 + (l & 15)) * EV_STRIDE + (l >> 4) * 16);
        a_hi[mt] = vb_hi + off;
        a_lo[mt] = vb_lo + off;
    }

    float acc[2][4][4] = {};
#pragma unroll
    for (int ks = 0; ks < 4; ks++) {
        uint32_t bh[2][4], bl[2][4];
#pragma unroll
        for (int G = 0; G < 2; G++) {
            *(uint4*)bh[G] = *(const uint4*)(g_Wm2F + ((ks * 2 + G) * 2 + 0) * 512 + l * 16);
            *(uint4*)bl[G] = *(const uint4*)(g_Wm2F + ((ks * 2 + G) * 2 + 1) * 512 + l * 16);
        }
        const uint32_t ko = ks * 32;
        uint32_t ah[2][4], al[2][4];
#pragma unroll
        for (int mt = 0; mt < 2; mt++) {
            LDSM_X4(ah[mt], a_hi[mt] + ko);
            LDSM_X4(al[mt], a_lo[mt] + ko);
        }
#pragma unroll
        for (int mt = 0; mt < 2; mt++) {
#pragma unroll
            for (int nt = 0; nt < 4; nt++) {
                const int gp = nt >> 1;
                const int br = (nt & 1) * 2;
                MMA_BF16(acc[mt][nt], ah[mt], bh[gp][br], bh[gp][br + 1]);
                MMA_BF16(acc[mt][nt], ah[mt], bl[gp][br], bl[gp][br + 1]);
                MMA_BF16(acc[mt][nt], al[mt], bh[gp][br], bh[gp][br + 1]);
            }
        }
    }

    float bm2v[4][2], wm3v[4][2];
#pragma unroll
    for (int nt = 0; nt < 4; nt++) {
        const int col = nt * 8 + 2 * (l & 3);
        bm2v[nt][0] = bm2[col];     bm2v[nt][1] = bm2[col + 1];
        wm3v[nt][0] = Wm3[col];     wm3v[nt][1] = Wm3[col + 1];
    }
    const float bm3v = bm3[0];

#pragma unroll
    for (int mt = 0; mt < 2; mt++) {
#pragma unroll
        for (int r = 0; r < 2; r++) {
            float s = 0.f;
#pragma unroll
            for (int nt = 0; nt < 4; nt++) {
                float c0 = fmaxf(acc[mt][nt][2 * r + 0] + bm2v[nt][0], 0.f);
                float c1 = fmaxf(acc[mt][nt][2 * r + 1] + bm2v[nt][1], 0.f);
                s = fmaf(c0, wm3v[nt][0], s);
                s = fmaf(c1, wm3v[nt][1], s);
            }
            s += __shfl_xor_sync(0xffffffffu, s, 1);
            s += __shfl_xor_sync(0xffffffffu, s, 2);
            if ((l & 3) == 0) {
                const int ge = e0 + w * 32 + mt * 16 + r * 8 + (l >> 2);
                if (ge < E) out[ge] = s + bm3v;
            }
        }
    }
}

// ---------------------------------------------------------------------------
extern "C" void kernel_launch(void* const* d_in, const int* in_sizes, int n_in,
                              void* d_out, int out_size) {
    const float* x_gene = (const float*)d_in[0];
    const float* x_cell = (const float*)d_in[1];
    const int*   eidx   = (const int*)  d_in[2];
    const float* W1     = (const float*)d_in[3];
    const float* b1     = (const float*)d_in[4];
    const float* W2     = (const float*)d_in[5];
    const float* b2     = (const float*)d_in[6];
    const float* Wm1    = (const float*)d_in[7];
    const float* bm1    = (const float*)d_in[8];
    const float* Wm2    = (const float*)d_in[9];
    const float* bm2    = (const float*)d_in[10];
    const float* Wm3    = (const float*)d_in[11];
    const float* bm3    = (const float*)d_in[12];
    float* out = (float*)d_out;

    const int N1 = in_sizes[0] / FDIM;
    const int N2 = in_sizes[1] / FDIM;
    const int E  = in_sizes[2] / 2;

    cudaFuncSetAttribute(proj_mma_kernel,
                         cudaFuncAttributeMaxDynamicSharedMemorySize, SM_TOTAL);

    fold_all_kernel<<<dim3(129, 2), 256>>>(W1, W2, Wm1, b1, b2, bm1, Wm2);

    const int Mmax = (N1 > N2) ? N1 : N2;
    proj_mma_kernel<<<dim3((Mmax + 127) / 128, 2), 256, SM_TOTAL>>>(x_gene, x_cell, N1, N2);

    edge_kernel<<<(E + 127) / 128, 128>>>(eidx, bm2, Wm3, bm3, out, E, N1, N2);
}

// round 16
// speedup vs baseline: 1.0193x; 1.0193x over previous
#include <cuda_runtime.h>
#include <cuda_bf16.h>
#include <cstdint>

// Problem constants (fixed by dataset: N1=N2=50000, F=1024, D=128, H1=64, H2=32, E=1e6)
#define FDIM  1024
#define DDIM  128
#define H1DIM 64
#define H2DIM 32
#define NMAX  50000

// ---------------------------------------------------------------------------
// Scratch (static device globals — no runtime allocation allowed)
// ---------------------------------------------------------------------------
__device__ __nv_bfloat16 g_WcTh[2 * H1DIM * FDIM];  // folded W, transposed [half][n][k], hi split
__device__ __nv_bfloat16 g_WcTl[2 * H1DIM * FDIM];  // lo split
__device__ __align__(16) unsigned char g_Wm2F[8192]; // Wm2 frag table (edge layer-2)
__device__ float g_bc1[H1DIM];
__device__ float g_bc2[H1DIM];
__device__ float g_g1[NMAX * H1DIM];    // x_gene @ Wc1 + bc1   [50000,64]
__device__ float g_g2[NMAX * H1DIM];    // x_cell @ Wc2 + bc2   [50000,64]

__device__ __forceinline__ uint32_t smem_u32(const void* p) {
    uint32_t a;
    asm("{ .reg .u64 t; cvta.to.shared.u64 t, %1; cvt.u32.u64 %0, t; }" : "=r"(a) : "l"(p));
    return a;
}

#define LDSM_X4(r, a) \
    asm volatile("ldmatrix.sync.aligned.m8n8.x4.shared.b16 {%0,%1,%2,%3}, [%4];" \
                 : "=r"((r)[0]), "=r"((r)[1]), "=r"((r)[2]), "=r"((r)[3]) : "r"(a))

#define MMA_BF16(c, a, b0, b1) \
    asm volatile("mma.sync.aligned.m16n8k16.row.col.f32.bf16.bf16.f32 " \
                 "{%0,%1,%2,%3}, {%4,%5,%6,%7}, {%8,%9}, {%0,%1,%2,%3};" \
                 : "+f"((c)[0]), "+f"((c)[1]), "+f"((c)[2]), "+f"((c)[3]) \
                 : "r"((a)[0]), "r"((a)[1]), "r"((a)[2]), "r"((a)[3]), "r"(b0), "r"(b1))

#define CP_ASYNC16(dst, src) \
    asm volatile("cp.async.ca.shared.global [%0], [%1], 16;" :: "r"(dst), "l"(src))
#define CP_COMMIT() asm volatile("cp.async.commit_group;" ::: "memory")
#define CP_WAIT1()  asm volatile("cp.async.wait_group 1;" ::: "memory")

__device__ __forceinline__ void split_bf16x2(float a, float b, uint32_t& hi, uint32_t& lo) {
    __nv_bfloat16 ha = __float2bfloat16(a);
    __nv_bfloat16 hb = __float2bfloat16(b);
    __nv_bfloat162 h = __halves2bfloat162(ha, hb);
    __nv_bfloat162 l = __floats2bfloat162_rn(a - __bfloat162float(ha),
                                             b - __bfloat162float(hb));
    hi = *(uint32_t*)&h;
    lo = *(uint32_t*)&l;
}

// ---------------------------------------------------------------------------
// Kernel 1: ALL folds in one launch — float4-vectorized, 8 f-rows per block.
// grid (129, 2), 256 threads. (R12 configuration — measured best, 13.9us.)
//   bx < 128         : weight fold (W @ Wm1half -> bf16 hi/lo, transposed)
//   bx == 128, by==0 : bias fold
//   bx == 128, by==1 : Wm2 -> mma-fragment table
// ---------------------------------------------------------------------------
#define BLKF 8

__global__ void __launch_bounds__(256)
fold_all_kernel(const float* __restrict__ W1,
                const float* __restrict__ W2,
                const float* __restrict__ Wm1,
                const float* __restrict__ b1,
                const float* __restrict__ b2,
                const float* __restrict__ bm1,
                const float* __restrict__ Wm2) {
    __shared__ float Wm1T[H1DIM][DDIM + 4];   // transposed: [j][d], 33.8KB
    __shared__ float Ws[BLKF][DDIM];          // 4KB

    const int t    = threadIdx.x;
    const int half = blockIdx.y;

    if (blockIdx.x < 128) {
        const int f0   = blockIdx.x * BLKF;
        const float* W = half ? W2 : W1;
        const int off  = half * DDIM;

        // Load Wm1 half transposed: Wm1T[j][d] = Wm1[(off+d)*64 + j]
        for (int i = t; i < DDIM * H1DIM; i += 256) {
            const int d = i >> 6;
            const int j = i & 63;
            Wm1T[j][d] = Wm1[(off + d) * H1DIM + j];
        }
        // Load W tile [8][128] coalesced
        for (int i = t; i < BLKF * DDIM; i += 256)
            Ws[i >> 7][i & 127] = W[(size_t)(f0 + (i >> 7)) * DDIM + (i & 127)];
        __syncthreads();

        const int j  = t & 63;
        const int fi = t >> 6;            // 0..3
#pragma unroll
        for (int r = 0; r < 2; r++) {
            const int fr = fi + 4 * r;    // 0..7
            float acc = 0.f;
#pragma unroll
            for (int d4 = 0; d4 < DDIM / 4; d4++) {
                const float4 wv = *(const float4*)&Ws[fr][d4 * 4];      // warp broadcast
                const float4 mv = *(const float4*)&Wm1T[j][d4 * 4];     // vector LDS
                acc = fmaf(wv.x, mv.x, acc);
                acc = fmaf(wv.y, mv.y, acc);
                acc = fmaf(wv.z, mv.z, acc);
                acc = fmaf(wv.w, mv.w, acc);
            }
            __nv_bfloat16 hi = __float2bfloat16(acc);
            __nv_bfloat16 lo = __float2bfloat16(acc - __bfloat162float(hi));
            const int idx = (half * H1DIM + j) * FDIM + (f0 + fr);
            g_WcTh[idx] = hi;
            g_WcTl[idx] = lo;
        }
    } else if (half == 0) {
        // Bias fold (threads 0..127)
        if (t >= 128) return;
        const int j = t & 63;
        const int h2 = t >> 6;
        const float* b = h2 ? b2 : b1;
        const int off = h2 * DDIM;
        float acc = h2 ? 0.f : bm1[j];
#pragma unroll 8
        for (int d = 0; d < DDIM; d++)
            acc = fmaf(b[d], Wm1[(off + d) * H1DIM + j], acc);
        (h2 ? g_bc2 : g_bc1)[j] = acc;
    } else {
        // Wm2 [64,32] -> bf16 hi/lo frag table (validated mapping)
        for (int idx = t; idx < H2DIM * H1DIM; idx += 256) {
            const int n = idx & (H2DIM - 1);
            const int k = idx >> 5;
            float v = Wm2[k * H2DIM + n];
            __nv_bfloat16 hi = __float2bfloat16(v);
            __nv_bfloat16 lo = __float2bfloat16(v - __bfloat162float(hi));
            const int ks = k >> 4, G = n >> 4, rr = n & 7, mh = (n >> 3) & 1, kb = k & 15;
            const int lane = rr * 4 + ((kb & 7) >> 1);
            const int reg  = mh * 2 + (kb >> 3);
            const int base = ((ks * 2 + G) * 2) * 512 + lane * 16 + reg * 4 + (kb & 1) * 2;
            *(__nv_bfloat16*)(g_Wm2F + base)       = hi;
            *(__nv_bfloat16*)(g_Wm2F + base + 512) = lo;
        }
    }
}

// ---------------------------------------------------------------------------
// Kernel 2: mma.sync bf16-split projection GEMM — proven 129.3-129.6us.
// A 2-stage smem double buffer, B 3-stage cp.async ring, one barrier/chunk.
// ---------------------------------------------------------------------------
#define A_STRIDE   80
#define A_ST_BYTES (128 * A_STRIDE)
#define B_STRIDE   80
#define B_ST_BYTES (H1DIM * B_STRIDE)
#define OFF_A_HI   0
#define OFF_A_LO   (2 * A_ST_BYTES)
#define OFF_B_HI   (4 * A_ST_BYTES)
#define OFF_B_LO   (OFF_B_HI + 3 * B_ST_BYTES)
#define SM_TOTAL   (OFF_B_LO + 3 * B_ST_BYTES)

__global__ void __launch_bounds__(256)
proj_mma_kernel(const float* __restrict__ x_gene,
                const float* __restrict__ x_cell,
                int N1, int N2) {
    extern __shared__ __align__(16) char smem[];

    const int t   = threadIdx.x;
    const int wid = t >> 5;
    const int l   = t & 31;
    const int half = blockIdx.y;

    const float* x = half ? x_cell : x_gene;
    const char* WTh = (const char*)(g_WcTh + half * H1DIM * FDIM);
    const char* WTl = (const char*)(g_WcTl + half * H1DIM * FDIM);
    const float* bc = half ? g_bc2 : g_bc1;
    float* g = half ? g_g2 : g_g1;
    const int M  = half ? N2 : N1;
    const int m0 = blockIdx.x * 128;
    if (m0 >= M) return;

    const uint32_t sb = smem_u32(smem);

    const int m0w = (wid & 3) * 32;
    const int n0w = (wid >> 2) * 32;

    float acc[2][4][4] = {};

    const float4* xv = (const float4*)x;
    const int arow = t >> 3;
    const int ac4  = t & 7;
    const int brow = t >> 2;
    const int bq   = t & 3;

    size_t gmr[4];
#pragma unroll
    for (int r = 0; r < 4; r++) {
        int gm = m0 + arow + 32 * r;
        gmr[r] = (size_t)((gm < M) ? gm : (M - 1));
    }

    uint32_t a_off[2], b_off[2];
#pragma unroll
    for (int mt = 0; mt < 2; mt++)
        a_off[mt] = (uint32_t)((m0w + mt * 16 + (l & 15)) * A_STRIDE + (l >> 4) * 16);
#pragma unroll
    for (int gp = 0; gp < 2; gp++)
        b_off[gp] = (uint32_t)((n0w + gp * 16 + ((l >> 4) * 8) + (l & 7)) * B_STRIDE
                               + ((l >> 3) & 1) * 16);

    const size_t bgo = (size_t)brow * (FDIM * 2) + bq * 16;
    const uint32_t bso = (uint32_t)(brow * B_STRIDE + bq * 16);
    const uint32_t a_sts = (uint32_t)(arow * A_STRIDE + ac4 * 8);

    float4 va[4];
#pragma unroll
    for (int r = 0; r < 4; r++) va[r] = xv[gmr[r] * (FDIM / 4) + ac4];
    CP_ASYNC16(sb + OFF_B_HI + bso, WTh + bgo);
    CP_ASYNC16(sb + OFF_B_LO + bso, WTl + bgo);
    CP_COMMIT();
    CP_ASYNC16(sb + OFF_B_HI + B_ST_BYTES + bso, WTh + bgo + 64);
    CP_ASYNC16(sb + OFF_B_LO + B_ST_BYTES + bso, WTl + bgo + 64);
    CP_COMMIT();
#pragma unroll
    for (int r = 0; r < 4; r++) {
        uint2 uh, ul;
        split_bf16x2(va[r].x, va[r].y, uh.x, ul.x);
        split_bf16x2(va[r].z, va[r].w, uh.y, ul.y);
        *(uint2*)(smem + OFF_A_HI + a_sts + 32 * r * A_STRIDE) = uh;
        *(uint2*)(smem + OFF_A_LO + a_sts + 32 * r * A_STRIDE) = ul;
    }
#pragma unroll
    for (int r = 0; r < 4; r++) va[r] = xv[gmr[r] * (FDIM / 4) + 8 + ac4];
    CP_WAIT1();
    __syncthreads();

    int b_cur = 0;
    for (int kk = 0; kk < FDIM / 32; kk++) {
        const int a_cur = kk & 1;
        if (kk < FDIM / 32 - 1) {
            const uint32_t abase = (uint32_t)((a_cur ^ 1) * A_ST_BYTES);
#pragma unroll
            for (int r = 0; r < 4; r++) {
                uint2 uh, ul;
                split_bf16x2(va[r].x, va[r].y, uh.x, ul.x);
                split_bf16x2(va[r].z, va[r].w, uh.y, ul.y);
                *(uint2*)(smem + OFF_A_HI + abase + a_sts + 32 * r * A_STRIDE) = uh;
                *(uint2*)(smem + OFF_A_LO + abase + a_sts + 32 * r * A_STRIDE) = ul;
            }
        }
        if (kk < FDIM / 32 - 2) {
#pragma unroll
            for (int r = 0; r < 4; r++)
                va[r] = xv[gmr[r] * (FDIM / 4) + (kk + 2) * 8 + ac4];
        }
        if (kk < FDIM / 32 - 2) {
            int b2 = b_cur + 2; if (b2 >= 3) b2 -= 3;
            const uint32_t nb = (uint32_t)(b2 * B_ST_BYTES);
            CP_ASYNC16(sb + OFF_B_HI + nb + bso, WTh + bgo + (size_t)(kk + 2) * 64);
            CP_ASYNC16(sb + OFF_B_LO + nb + bso, WTl + bgo + (size_t)(kk + 2) * 64);
        }
        CP_COMMIT();

        const uint32_t ah_base = sb + OFF_A_HI + a_cur * A_ST_BYTES;
        const uint32_t al_base = sb + OFF_A_LO + a_cur * A_ST_BYTES;
        const uint32_t bh_base = sb + OFF_B_HI + b_cur * B_ST_BYTES;
        const uint32_t bl_base = sb + OFF_B_LO + b_cur * B_ST_BYTES;
#pragma unroll
        for (int kc = 0; kc < 2; kc++) {
            const uint32_t ko = kc * 32;
            uint32_t ah[2][4], al[2][4], bh[2][4], bl[2][4];
#pragma unroll
            for (int mt = 0; mt < 2; mt++) {
                LDSM_X4(ah[mt], ah_base + a_off[mt] + ko);
                LDSM_X4(al[mt], al_base + a_off[mt] + ko);
            }
#pragma unroll
            for (int gp = 0; gp < 2; gp++) {
                LDSM_X4(bh[gp], bh_base + b_off[gp] + ko);
                LDSM_X4(bl[gp], bl_base + b_off[gp] + ko);
            }
#pragma unroll
            for (int mt = 0; mt < 2; mt++) {
#pragma unroll
                for (int nt = 0; nt < 4; nt++) {
                    const int gp = nt >> 1;
                    const int br = (nt & 1) * 2;
                    MMA_BF16(acc[mt][nt], ah[mt], bh[gp][br], bh[gp][br + 1]);
                    MMA_BF16(acc[mt][nt], ah[mt], bl[gp][br], bl[gp][br + 1]);
                    MMA_BF16(acc[mt][nt], al[mt], bh[gp][br], bh[gp][br + 1]);
                }
            }
        }
        CP_WAIT1();
        __syncthreads();
        b_cur = (b_cur == 2) ? 0 : b_cur + 1;
    }

#pragma unroll
    for (int mt = 0; mt < 2; mt++) {
#pragma unroll
        for (int nt = 0; nt < 4; nt++) {
            const int col = n0w + nt * 8 + 2 * (l & 3);
            const float bx = bc[col], by = bc[col + 1];
            const int r0 = m0 + m0w + mt * 16 + (l >> 2);
            if (r0 < M) {
                float2 o; o.x = acc[mt][nt][0] + bx; o.y = acc[mt][nt][1] + by;
                *(float2*)&g[(size_t)r0 * H1DIM + col] = o;
            }
            const int r1 = r0 + 8;
            if (r1 < M) {
                float2 o; o.x = acc[mt][nt][2] + bx; o.y = acc[mt][nt][3] + by;
                *(float2*)&g[(size_t)r1 * H1DIM + col] = o;
            }
        }
    }
}

// ---------------------------------------------------------------------------
// Kernel 3: barrier-free edge stage — proven, measured 58.9us.
// ---------------------------------------------------------------------------
#define EV_STRIDE 144

__global__ void __launch_bounds__(128)
edge_kernel(const int* __restrict__ eidx,
            const float* __restrict__ bm2,
            const float* __restrict__ Wm3,
            const float* __restrict__ bm3,
            float* __restrict__ out,
            int E, int N1, int N2) {
    __shared__ __align__(16) char vhi[128 * EV_STRIDE];
    __shared__ __align__(16) char vlo[128 * EV_STRIDE];

    const int t  = threadIdx.x;
    const int w  = t >> 5;
    const int l  = t & 31;
    const int e0 = blockIdx.x * 128;

    int s_l, d_l;
    {
        int eg = e0 + w * 32 + l;
        int ec = (eg < E) ? eg : (E - 1);
        int s = eidx[ec];
        int d = eidx[E + ec];
        s_l = (s < 0) ? 0 : (s >= N1 ? N1 - 1 : s);
        d_l = (d < 0) ? 0 : (d >= N2 ? N2 - 1 : d);
    }

    const float4* g1v = (const float4*)g_g1;
    const float4* g2v = (const float4*)g_g2;
    const int c = l & 15;
#pragma unroll
    for (int it = 0; it < 16; it++) {
        const int e = (l >> 4) + 2 * it;
        const int si = __shfl_sync(0xffffffffu, s_l, e);
        const int di = __shfl_sync(0xffffffffu, d_l, e);
        float4 a = g1v[si * 16 + c];
        float4 b = g2v[di * 16 + c];
        float v0 = fmaxf(a.x + b.x, 0.f);
        float v1 = fmaxf(a.y + b.y, 0.f);
        float v2 = fmaxf(a.z + b.z, 0.f);
        float v3 = fmaxf(a.w + b.w, 0.f);
        uint2 uh, ul;
        split_bf16x2(v0, v1, uh.x, ul.x);
        split_bf16x2(v2, v3, uh.y, ul.y);
        const uint32_t off = (uint32_t)((w * 32 + e) * EV_STRIDE + c * 8);
        *(uint2*)(vhi + off) = uh;
        *(uint2*)(vlo + off) = ul;
    }
    __syncwarp();

    const uint32_t vb_hi = smem_u32(vhi);
    const uint32_t vb_lo = smem_u32(vlo);
    uint32_t a_hi[2], a_lo[2];
#pragma unroll
    for (int mt = 0; mt < 2; mt++) {
        const uint32_t off = (uint32_t)((w * 32 + mt * 16 + (l & 15)) * EV_STRIDE + (l >> 4) * 16);
        a_hi[mt] = vb_hi + off;
        a_lo[mt] = vb_lo + off;
    }

    float acc[2][4][4] = {};
#pragma unroll
    for (int ks = 0; ks < 4; ks++) {
        uint32_t bh[2][4], bl[2][4];
#pragma unroll
        for (int G = 0; G < 2; G++) {
            *(uint4*)bh[G] = *(const uint4*)(g_Wm2F + ((ks * 2 + G) * 2 + 0) * 512 + l * 16);
            *(uint4*)bl[G] = *(const uint4*)(g_Wm2F + ((ks * 2 + G) * 2 + 1) * 512 + l * 16);
        }
        const uint32_t ko = ks * 32;
        uint32_t ah[2][4], al[2][4];
#pragma unroll
        for (int mt = 0; mt < 2; mt++) {
            LDSM_X4(ah[mt], a_hi[mt] + ko);
            LDSM_X4(al[mt], a_lo[mt] + ko);
        }
#pragma unroll
        for (int mt = 0; mt < 2; mt++) {
#pragma unroll
            for (int nt = 0; nt < 4; nt++) {
                const int gp = nt >> 1;
                const int br = (nt & 1) * 2;
                MMA_BF16(acc[mt][nt], ah[mt], bh[gp][br], bh[gp][br + 1]);
                MMA_BF16(acc[mt][nt], ah[mt], bl[gp][br], bl[gp][br + 1]);
                MMA_BF16(acc[mt][nt], al[mt], bh[gp][br], bh[gp][br + 1]);
            }
        }
    }

    float bm2v[4][2], wm3v[4][2];
#pragma unroll
    for (int nt = 0; nt < 4; nt++) {
        const int col = nt * 8 + 2 * (l & 3);
        bm2v[nt][0] = bm2[col];     bm2v[nt][1] = bm2[col + 1];
        wm3v[nt][0] = Wm3[col];     wm3v[nt][1] = Wm3[col + 1];
    }
    const float bm3v = bm3[0];

#pragma unroll
    for (int mt = 0; mt < 2; mt++) {
#pragma unroll
        for (int r = 0; r < 2; r++) {
            float s = 0.f;
#pragma unroll
            for (int nt = 0; nt < 4; nt++) {
                float c0 = fmaxf(acc[mt][nt][2 * r + 0] + bm2v[nt][0], 0.f);
                float c1 = fmaxf(acc[mt][nt][2 * r + 1] + bm2v[nt][1], 0.f);
                s = fmaf(c0, wm3v[nt][0], s);
                s = fmaf(c1, wm3v[nt][1], s);
            }
            s += __shfl_xor_sync(0xffffffffu, s, 1);
            s += __shfl_xor_sync(0xffffffffu, s, 2);
            if ((l & 3) == 0) {
                const int ge = e0 + w * 32 + mt * 16 + r * 8 + (l >> 2);
                if (ge < E) out[ge] = s + bm3v;
            }
        }
    }
}

// ---------------------------------------------------------------------------
extern "C" void kernel_launch(void* const* d_in, const int* in_sizes, int n_in,
                              void* d_out, int out_size) {
    const float* x_gene = (const float*)d_in[0];
    const float* x_cell = (const float*)d_in[1];
    const int*   eidx   = (const int*)  d_in[2];
    const float* W1     = (const float*)d_in[3];
    const float* b1     = (const float*)d_in[4];
    const float* W2     = (const float*)d_in[5];
    const float* b2     = (const float*)d_in[6];
    const float* Wm1    = (const float*)d_in[7];
    const float* bm1    = (const float*)d_in[8];
    const float* Wm2    = (const float*)d_in[9];
    const float* bm2    = (const float*)d_in[10];
    const float* Wm3    = (const float*)d_in[11];
    const float* bm3    = (const float*)d_in[12];
    float* out = (float*)d_out;

    const int N1 = in_sizes[0] / FDIM;
    const int N2 = in_sizes[1] / FDIM;
    const int E  = in_sizes[2] / 2;

    cudaFuncSetAttribute(proj_mma_kernel,
                         cudaFuncAttributeMaxDynamicSharedMemorySize, SM_TOTAL);

    fold_all_kernel<<<dim3(129, 2), 256>>>(W1, W2, Wm1, b1, b2, bm1, Wm2);

    const int Mmax = (N1 > N2) ? N1 : N2;
    proj_mma_kernel<<<dim3((Mmax + 127) / 128, 2), 256, SM_TOTAL>>>(x_gene, x_cell, N1, N2);

    edge_kernel<<<(E + 127) / 128, 128>>>(eidx, bm2, Wm3, bm3, out, E, N1, N2);
}

// round 17
// speedup vs baseline: 1.0373x; 1.0177x over previous
#include <cuda_runtime.h>
#include <cuda_bf16.h>
#include <cstdint>

// Problem constants (fixed by dataset: N1=N2=50000, F=1024, D=128, H1=64, H2=32, E=1e6)
#define FDIM  1024
#define DDIM  128
#define H1DIM 64
#define H2DIM 32
#define NMAX  50000

// ---------------------------------------------------------------------------
// Scratch (static device globals — no runtime allocation allowed)
// ---------------------------------------------------------------------------
__device__ __nv_bfloat16 g_WcTh[2 * H1DIM * FDIM];  // folded W, transposed [half][n][k], hi split
__device__ __nv_bfloat16 g_WcTl[2 * H1DIM * FDIM];  // lo split
__device__ __align__(16) unsigned char g_Wm2F[8192]; // Wm2 frag table (edge layer-2)
__device__ float g_bc1[H1DIM];
__device__ float g_bc2[H1DIM];
__device__ float g_g1[NMAX * H1DIM];    // x_gene @ Wc1 + bc1   [50000,64]
__device__ float g_g2[NMAX * H1DIM];    // x_cell @ Wc2 + bc2   [50000,64]

__device__ __forceinline__ uint32_t smem_u32(const void* p) {
    uint32_t a;
    asm("{ .reg .u64 t; cvta.to.shared.u64 t, %1; cvt.u32.u64 %0, t; }" : "=r"(a) : "l"(p));
    return a;
}

#define LDSM_X4(r, a) \
    asm volatile("ldmatrix.sync.aligned.m8n8.x4.shared.b16 {%0,%1,%2,%3}, [%4];" \
                 : "=r"((r)[0]), "=r"((r)[1]), "=r"((r)[2]), "=r"((r)[3]) : "r"(a))

#define MMA_BF16(c, a, b0, b1) \
    asm volatile("mma.sync.aligned.m16n8k16.row.col.f32.bf16.bf16.f32 " \
                 "{%0,%1,%2,%3}, {%4,%5,%6,%7}, {%8,%9}, {%0,%1,%2,%3};" \
                 : "+f"((c)[0]), "+f"((c)[1]), "+f"((c)[2]), "+f"((c)[3]) \
                 : "r"((a)[0]), "r"((a)[1]), "r"((a)[2]), "r"((a)[3]), "r"(b0), "r"(b1))

#define CP_ASYNC16(dst, src) \
    asm volatile("cp.async.ca.shared.global [%0], [%1], 16;" :: "r"(dst), "l"(src))
#define CP_COMMIT() asm volatile("cp.async.commit_group;" ::: "memory")
#define CP_WAIT1()  asm volatile("cp.async.wait_group 1;" ::: "memory")

__device__ __forceinline__ void split_bf16x2(float a, float b, uint32_t& hi, uint32_t& lo) {
    __nv_bfloat16 ha = __float2bfloat16(a);
    __nv_bfloat16 hb = __float2bfloat16(b);
    __nv_bfloat162 h = __halves2bfloat162(ha, hb);
    __nv_bfloat162 l = __floats2bfloat162_rn(a - __bfloat162float(ha),
                                             b - __bfloat162float(hb));
    hi = *(uint32_t*)&h;
    lo = *(uint32_t*)&l;
}

// ---------------------------------------------------------------------------
// Kernel 1: ALL folds in one launch — float4-vectorized, 8 f-rows per block.
// grid (129, 2), 256 threads. (R12/R16 configuration — measured best, ~14us;
// fill loops given explicit unroll hints to raise front-batched LDG MLP.)
//   bx < 128         : weight fold (W @ Wm1half -> bf16 hi/lo, transposed)
//   bx == 128, by==0 : bias fold
//   bx == 128, by==1 : Wm2 -> mma-fragment table
// ---------------------------------------------------------------------------
#define BLKF 8

__global__ void __launch_bounds__(256)
fold_all_kernel(const float* __restrict__ W1,
                const float* __restrict__ W2,
                const float* __restrict__ Wm1,
                const float* __restrict__ b1,
                const float* __restrict__ b2,
                const float* __restrict__ bm1,
                const float* __restrict__ Wm2) {
    __shared__ float Wm1T[H1DIM][DDIM + 4];   // transposed: [j][d], 33.8KB
    __shared__ float Ws[BLKF][DDIM];          // 4KB

    const int t    = threadIdx.x;
    const int half = blockIdx.y;

    if (blockIdx.x < 128) {
        const int f0   = blockIdx.x * BLKF;
        const float* W = half ? W2 : W1;
        const int off  = half * DDIM;

        // Load Wm1 half transposed: Wm1T[j][d] = Wm1[(off+d)*64 + j]
#pragma unroll 8
        for (int i = t; i < DDIM * H1DIM; i += 256) {
            const int d = i >> 6;
            const int j = i & 63;
            Wm1T[j][d] = Wm1[(off + d) * H1DIM + j];
        }
        // Load W tile [8][128] coalesced
#pragma unroll 4
        for (int i = t; i < BLKF * DDIM; i += 256)
            Ws[i >> 7][i & 127] = W[(size_t)(f0 + (i >> 7)) * DDIM + (i & 127)];
        __syncthreads();

        const int j  = t & 63;
        const int fi = t >> 6;            // 0..3
#pragma unroll
        for (int r = 0; r < 2; r++) {
            const int fr = fi + 4 * r;    // 0..7
            float acc = 0.f;
#pragma unroll
            for (int d4 = 0; d4 < DDIM / 4; d4++) {
                const float4 wv = *(const float4*)&Ws[fr][d4 * 4];      // warp broadcast
                const float4 mv = *(const float4*)&Wm1T[j][d4 * 4];     // vector LDS
                acc = fmaf(wv.x, mv.x, acc);
                acc = fmaf(wv.y, mv.y, acc);
                acc = fmaf(wv.z, mv.z, acc);
                acc = fmaf(wv.w, mv.w, acc);
            }
            __nv_bfloat16 hi = __float2bfloat16(acc);
            __nv_bfloat16 lo = __float2bfloat16(acc - __bfloat162float(hi));
            const int idx = (half * H1DIM + j) * FDIM + (f0 + fr);
            g_WcTh[idx] = hi;
            g_WcTl[idx] = lo;
        }
    } else if (half == 0) {
        // Bias fold (threads 0..127)
        if (t >= 128) return;
        const int j = t & 63;
        const int h2 = t >> 6;
        const float* b = h2 ? b2 : b1;
        const int off = h2 * DDIM;
        float acc = h2 ? 0.f : bm1[j];
#pragma unroll 8
        for (int d = 0; d < DDIM; d++)
            acc = fmaf(b[d], Wm1[(off + d) * H1DIM + j], acc);
        (h2 ? g_bc2 : g_bc1)[j] = acc;
    } else {
        // Wm2 [64,32] -> bf16 hi/lo frag table (validated mapping)
        for (int idx = t; idx < H2DIM * H1DIM; idx += 256) {
            const int n = idx & (H2DIM - 1);
            const int k = idx >> 5;
            float v = Wm2[k * H2DIM + n];
            __nv_bfloat16 hi = __float2bfloat16(v);
            __nv_bfloat16 lo = __float2bfloat16(v - __bfloat162float(hi));
            const int ks = k >> 4, G = n >> 4, rr = n & 7, mh = (n >> 3) & 1, kb = k & 15;
            const int lane = rr * 4 + ((kb & 7) >> 1);
            const int reg  = mh * 2 + (kb >> 3);
            const int base = ((ks * 2 + G) * 2) * 512 + lane * 16 + reg * 4 + (kb & 1) * 2;
            *(__nv_bfloat16*)(g_Wm2F + base)       = hi;
            *(__nv_bfloat16*)(g_Wm2F + base + 512) = lo;
        }
    }
}

// ---------------------------------------------------------------------------
// Kernel 2: mma.sync bf16-split projection GEMM — proven 129.3-129.6us.
// A 2-stage smem double buffer, B 3-stage cp.async ring, one barrier/chunk.
// ---------------------------------------------------------------------------
#define A_STRIDE   80
#define A_ST_BYTES (128 * A_STRIDE)
#define B_STRIDE   80
#define B_ST_BYTES (H1DIM * B_STRIDE)
#define OFF_A_HI   0
#define OFF_A_LO   (2 * A_ST_BYTES)
#define OFF_B_HI   (4 * A_ST_BYTES)
#define OFF_B_LO   (OFF_B_HI + 3 * B_ST_BYTES)
#define SM_TOTAL   (OFF_B_LO + 3 * B_ST_BYTES)

__global__ void __launch_bounds__(256)
proj_mma_kernel(const float* __restrict__ x_gene,
                const float* __restrict__ x_cell,
                int N1, int N2) {
    extern __shared__ __align__(16) char smem[];

    const int t   = threadIdx.x;
    const int wid = t >> 5;
    const int l   = t & 31;
    const int half = blockIdx.y;

    const float* x = half ? x_cell : x_gene;
    const char* WTh = (const char*)(g_WcTh + half * H1DIM * FDIM);
    const char* WTl = (const char*)(g_WcTl + half * H1DIM * FDIM);
    const float* bc = half ? g_bc2 : g_bc1;
    float* g = half ? g_g2 : g_g1;
    const int M  = half ? N2 : N1;
    const int m0 = blockIdx.x * 128;
    if (m0 >= M) return;

    const uint32_t sb = smem_u32(smem);

    const int m0w = (wid & 3) * 32;
    const int n0w = (wid >> 2) * 32;

    float acc[2][4][4] = {};

    const float4* xv = (const float4*)x;
    const int arow = t >> 3;
    const int ac4  = t & 7;
    const int brow = t >> 2;
    const int bq   = t & 3;

    size_t gmr[4];
#pragma unroll
    for (int r = 0; r < 4; r++) {
        int gm = m0 + arow + 32 * r;
        gmr[r] = (size_t)((gm < M) ? gm : (M - 1));
    }

    uint32_t a_off[2], b_off[2];
#pragma unroll
    for (int mt = 0; mt < 2; mt++)
        a_off[mt] = (uint32_t)((m0w + mt * 16 + (l & 15)) * A_STRIDE + (l >> 4) * 16);
#pragma unroll
    for (int gp = 0; gp < 2; gp++)
        b_off[gp] = (uint32_t)((n0w + gp * 16 + ((l >> 4) * 8) + (l & 7)) * B_STRIDE
                               + ((l >> 3) & 1) * 16);

    const size_t bgo = (size_t)brow * (FDIM * 2) + bq * 16;
    const uint32_t bso = (uint32_t)(brow * B_STRIDE + bq * 16);
    const uint32_t a_sts = (uint32_t)(arow * A_STRIDE + ac4 * 8);

    float4 va[4];
#pragma unroll
    for (int r = 0; r < 4; r++) va[r] = xv[gmr[r] * (FDIM / 4) + ac4];
    CP_ASYNC16(sb + OFF_B_HI + bso, WTh + bgo);
    CP_ASYNC16(sb + OFF_B_LO + bso, WTl + bgo);
    CP_COMMIT();
    CP_ASYNC16(sb + OFF_B_HI + B_ST_BYTES + bso, WTh + bgo + 64);
    CP_ASYNC16(sb + OFF_B_LO + B_ST_BYTES + bso, WTl + bgo + 64);
    CP_COMMIT();
#pragma unroll
    for (int r = 0; r < 4; r++) {
        uint2 uh, ul;
        split_bf16x2(va[r].x, va[r].y, uh.x, ul.x);
        split_bf16x2(va[r].z, va[r].w, uh.y, ul.y);
        *(uint2*)(smem + OFF_A_HI + a_sts + 32 * r * A_STRIDE) = uh;
        *(uint2*)(smem + OFF_A_LO + a_sts + 32 * r * A_STRIDE) = ul;
    }
#pragma unroll
    for (int r = 0; r < 4; r++) va[r] = xv[gmr[r] * (FDIM / 4) + 8 + ac4];
    CP_WAIT1();
    __syncthreads();

    int b_cur = 0;
    for (int kk = 0; kk < FDIM / 32; kk++) {
        const int a_cur = kk & 1;
        if (kk < FDIM / 32 - 1) {
            const uint32_t abase = (uint32_t)((a_cur ^ 1) * A_ST_BYTES);
#pragma unroll
            for (int r = 0; r < 4; r++) {
                uint2 uh, ul;
                split_bf16x2(va[r].x, va[r].y, uh.x, ul.x);
                split_bf16x2(va[r].z, va[r].w, uh.y, ul.y);
                *(uint2*)(smem + OFF_A_HI + abase + a_sts + 32 * r * A_STRIDE) = uh;
                *(uint2*)(smem + OFF_A_LO + abase + a_sts + 32 * r * A_STRIDE) = ul;
            }
        }
        if (kk < FDIM / 32 - 2) {
#pragma unroll
            for (int r = 0; r < 4; r++)
                va[r] = xv[gmr[r] * (FDIM / 4) + (kk + 2) * 8 + ac4];
        }
        if (kk < FDIM / 32 - 2) {
            int b2 = b_cur + 2; if (b2 >= 3) b2 -= 3;
            const uint32_t nb = (uint32_t)(b2 * B_ST_BYTES);
            CP_ASYNC16(sb + OFF_B_HI + nb + bso, WTh + bgo + (size_t)(kk + 2) * 64);
            CP_ASYNC16(sb + OFF_B_LO + nb + bso, WTl + bgo + (size_t)(kk + 2) * 64);
        }
        CP_COMMIT();

        const uint32_t ah_base = sb + OFF_A_HI + a_cur * A_ST_BYTES;
        const uint32_t al_base = sb + OFF_A_LO + a_cur * A_ST_BYTES;
        const uint32_t bh_base = sb + OFF_B_HI + b_cur * B_ST_BYTES;
        const uint32_t bl_base = sb + OFF_B_LO + b_cur * B_ST_BYTES;
#pragma unroll
        for (int kc = 0; kc < 2; kc++) {
            const uint32_t ko = kc * 32;
            uint32_t ah[2][4], al[2][4], bh[2][4], bl[2][4];
#pragma unroll
            for (int mt = 0; mt < 2; mt++) {
                LDSM_X4(ah[mt], ah_base + a_off[mt] + ko);
                LDSM_X4(al[mt], al_base + a_off[mt] + ko);
            }
#pragma unroll
            for (int gp = 0; gp < 2; gp++) {
                LDSM_X4(bh[gp], bh_base + b_off[gp] + ko);
                LDSM_X4(bl[gp], bl_base + b_off[gp] + ko);
            }
#pragma unroll
            for (int mt = 0; mt < 2; mt++) {
#pragma unroll
                for (int nt = 0; nt < 4; nt++) {
                    const int gp = nt >> 1;
                    const int br = (nt & 1) * 2;
                    MMA_BF16(acc[mt][nt], ah[mt], bh[gp][br], bh[gp][br + 1]);
                    MMA_BF16(acc[mt][nt], ah[mt], bl[gp][br], bl[gp][br + 1]);
                    MMA_BF16(acc[mt][nt], al[mt], bh[gp][br], bh[gp][br + 1]);
                }
            }
        }
        CP_WAIT1();
        __syncthreads();
        b_cur = (b_cur == 2) ? 0 : b_cur + 1;
    }

#pragma unroll
    for (int mt = 0; mt < 2; mt++) {
#pragma unroll
        for (int nt = 0; nt < 4; nt++) {
            const int col = n0w + nt * 8 + 2 * (l & 3);
            const float bx = bc[col], by = bc[col + 1];
            const int r0 = m0 + m0w + mt * 16 + (l >> 2);
            if (r0 < M) {
                float2 o; o.x = acc[mt][nt][0] + bx; o.y = acc[mt][nt][1] + by;
                *(float2*)&g[(size_t)r0 * H1DIM + col] = o;
            }
            const int r1 = r0 + 8;
            if (r1 < M) {
                float2 o; o.x = acc[mt][nt][2] + bx; o.y = acc[mt][nt][3] + by;
                *(float2*)&g[(size_t)r1 * H1DIM + col] = o;
            }
        }
    }
}

// ---------------------------------------------------------------------------
// Kernel 3: barrier-free edge stage — proven, measured 58.9us.
// ---------------------------------------------------------------------------
#define EV_STRIDE 144

__global__ void __launch_bounds__(128)
edge_kernel(const int* __restrict__ eidx,
            const float* __restrict__ bm2,
            const float* __restrict__ Wm3,
            const float* __restrict__ bm3,
            float* __restrict__ out,
            int E, int N1, int N2) {
    __shared__ __align__(16) char vhi[128 * EV_STRIDE];
    __shared__ __align__(16) char vlo[128 * EV_STRIDE];

    const int t  = threadIdx.x;
    const int w  = t >> 5;
    const int l  = t & 31;
    const int e0 = blockIdx.x * 128;

    int s_l, d_l;
    {
        int eg = e0 + w * 32 + l;
        int ec = (eg < E) ? eg : (E - 1);
        int s = eidx[ec];
        int d = eidx[E + ec];
        s_l = (s < 0) ? 0 : (s >= N1 ? N1 - 1 : s);
        d_l = (d < 0) ? 0 : (d >= N2 ? N2 - 1 : d);
    }

    const float4* g1v = (const float4*)g_g1;
    const float4* g2v = (const float4*)g_g2;
    const int c = l & 15;
#pragma unroll
    for (int it = 0; it < 16; it++) {
        const int e = (l >> 4) + 2 * it;
        const int si = __shfl_sync(0xffffffffu, s_l, e);
        const int di = __shfl_sync(0xffffffffu, d_l, e);
        float4 a = g1v[si * 16 + c];
        float4 b = g2v[di * 16 + c];
        float v0 = fmaxf(a.x + b.x, 0.f);
        float v1 = fmaxf(a.y + b.y, 0.f);
        float v2 = fmaxf(a.z + b.z, 0.f);
        float v3 = fmaxf(a.w + b.w, 0.f);
        uint2 uh, ul;
        split_bf16x2(v0, v1, uh.x, ul.x);
        split_bf16x2(v2, v3, uh.y, ul.y);
        const uint32_t off = (uint32_t)((w * 32 + e) * EV_STRIDE + c * 8);
        *(uint2*)(vhi + off) = uh;
        *(uint2*)(vlo + off) = ul;
    }
    __syncwarp();

    const uint32_t vb_hi = smem_u32(vhi);
    const uint32_t vb_lo = smem_u32(vlo);
    uint32_t a_hi[2], a_lo[2];
#pragma unroll
    for (int mt = 0; mt < 2; mt++) {
        const uint32_t off = (uint32_t)((w * 32 + mt * 16 + (l & 15)) * EV_STRIDE + (l >> 4) * 16);
        a_hi[mt] = vb_hi + off;
        a_lo[mt] = vb_lo + off;
    }

    float acc[2][4][4] = {};
#pragma unroll
    for (int ks = 0; ks < 4; ks++) {
        uint32_t bh[2][4], bl[2][4];
#pragma unroll
        for (int G = 0; G < 2; G++) {
            *(uint4*)bh[G] = *(const uint4*)(g_Wm2F + ((ks * 2 + G) * 2 + 0) * 512 + l * 16);
            *(uint4*)bl[G] = *(const uint4*)(g_Wm2F + ((ks * 2 + G) * 2 + 1) * 512 + l * 16);
        }
        const uint32_t ko = ks * 32;
        uint32_t ah[2][4], al[2][4];
#pragma unroll
        for (int mt = 0; mt < 2; mt++) {
            LDSM_X4(ah[mt], a_hi[mt] + ko);
            LDSM_X4(al[mt], a_lo[mt] + ko);
        }
#pragma unroll
        for (int mt = 0; mt < 2; mt++) {
#pragma unroll
            for (int nt = 0; nt < 4; nt++) {
                const int gp = nt >> 1;
                const int br = (nt & 1) * 2;
                MMA_BF16(acc[mt][nt], ah[mt], bh[gp][br], bh[gp][br + 1]);
                MMA_BF16(acc[mt][nt], ah[mt], bl[gp][br], bl[gp][br + 1]);
                MMA_BF16(acc[mt][nt], al[mt], bh[gp][br], bh[gp][br + 1]);
            }
        }
    }

    float bm2v[4][2], wm3v[4][2];
#pragma unroll
    for (int nt = 0; nt < 4; nt++) {
        const int col = nt * 8 + 2 * (l & 3);
        bm2v[nt][0] = bm2[col];     bm2v[nt][1] = bm2[col + 1];
        wm3v[nt][0] = Wm3[col];     wm3v[nt][1] = Wm3[col + 1];
    }
    const float bm3v = bm3[0];

#pragma unroll
    for (int mt = 0; mt < 2; mt++) {
#pragma unroll
        for (int r = 0; r < 2; r++) {
            float s = 0.f;
#pragma unroll
            for (int nt = 0; nt < 4; nt++) {
                float c0 = fmaxf(acc[mt][nt][2 * r + 0] + bm2v[nt][0], 0.f);
                float c1 = fmaxf(acc[mt][nt][2 * r + 1] + bm2v[nt][1], 0.f);
                s = fmaf(c0, wm3v[nt][0], s);
                s = fmaf(c1, wm3v[nt][1], s);
            }
            s += __shfl_xor_sync(0xffffffffu, s, 1);
            s += __shfl_xor_sync(0xffffffffu, s, 2);
            if ((l & 3) == 0) {
                const int ge = e0 + w * 32 + mt * 16 + r * 8 + (l >> 2);
                if (ge < E) out[ge] = s + bm3v;
            }
        }
    }
}

// ---------------------------------------------------------------------------
extern "C" void kernel_launch(void* const* d_in, const int* in_sizes, int n_in,
                              void* d_out, int out_size) {
    const float* x_gene = (const float*)d_in[0];
    const float* x_cell = (const float*)d_in[1];
    const int*   eidx   = (const int*)  d_in[2];
    const float* W1     = (const float*)d_in[3];
    const float* b1     = (const float*)d_in[4];
    const float* W2     = (const float*)d_in[5];
    const float* b2     = (const float*)d_in[6];
    const float* Wm1    = (const float*)d_in[7];
    const float* bm1    = (const float*)d_in[8];
    const float* Wm2    = (const float*)d_in[9];
    const float* bm2    = (const float*)d_in[10];
    const float* Wm3    = (const float*)d_in[11];
    const float* bm3    = (const float*)d_in[12];
    float* out = (float*)d_out;

    const int N1 = in_sizes[0] / FDIM;
    const int N2 = in_sizes[1] / FDIM;
    const int E  = in_sizes[2] / 2;

    cudaFuncSetAttribute(proj_mma_kernel,
                         cudaFuncAttributeMaxDynamicSharedMemorySize, SM_TOTAL);

    fold_all_kernel<<<dim3(129, 2), 256>>>(W1, W2, Wm1, b1, b2, bm1, Wm2);

    const int Mmax = (N1 > N2) ? N1 : N2;
    proj_mma_kernel<<<dim3((Mmax + 127) / 128, 2), 256, SM_TOTAL>>>(x_gene, x_cell, N1, N2);

    edge_kernel<<<(E + 127) / 128, 128>>>(eidx, bm2, Wm3, bm3, out, E, N1, N2);
}